// round 15
// baseline (speedup 1.0000x reference)
#include <cuda_runtime.h>
#include <cuda_fp16.h>
#include <cstdint>

#define NN   4096
#define FIN  128
#define FOUT 64
#define NH   8
#define CT   1024
#define SLOPE 0.2f
#define BS_H 144   // halves per B smem row: 128 data + 16 pad (word-stride 72 ≡ 8 mod 32)
#define LOG2E 1.4426950408889634f

// ---------------- scratch (device globals; no allocations) ----------------
__device__ float    g_hs[NN * CT];            // [n][1024]: 0..511 h per head, 512..1023 skip
__device__ __half   g_hH[NH * FOUT * NN];     // [h][o][j], f16, j 16-groups frag-permuted
__device__ float    g_ssrc[NH * NN];          // pre-scaled by log2(e)
__device__ float    g_sdst[NH * NN];          // pre-scaled by log2(e)
__device__ unsigned g_maskT[(NN / 32) * NN];  // [word w][i] transposed adjacency bitmask
__device__ float    g_attnP[2][NH * NN * FOUT]; // per-j-half unnormalized partials
__device__ float    g_rsP[2][NH * NN];          // per-j-half partial row sums

__device__ __forceinline__ uint32_t smem_u32(const void* p) {
    uint32_t a;
    asm("{ .reg .u64 t; cvta.to.shared.u64 t, %1; cvt.u32.u64 %0, t; }" : "=r"(a) : "l"(p));
    return a;
}

__device__ __forceinline__ float rndtf32(float v) {
    uint32_t u;
    asm("cvt.rna.tf32.f32 %0, %1;" : "=r"(u) : "f"(v));
    return __uint_as_float(u);
}

// ============ fused prep: blocks 0-255 GEMM, blocks 256+ mask =============
// GEMM (tf32 tensor cores): g_hs = x @ W^T, W gathered inline from proj/skw.
// Mask: adjacency bitmask via ballot (transposed [word][i]).
__global__ void __launch_bounds__(256) k_prep(const float* __restrict__ x,
                                              const float* __restrict__ topo,
                                              const float* __restrict__ proj,
                                              const float* __restrict__ skw) {
    __shared__ float sA[128][36];
    __shared__ float sB[128][36];
    int bid = blockIdx.x, tid = threadIdx.x;

    if (bid >= 256) {
        // ---------------- mask part (memory-bound, overlaps GEMM) ---------
        int wt = (bid - 256) * 8 + (tid >> 5);   // 0..131071
        int lane = tid & 31;
        int i = wt >> 5, w4 = (wt & 31) * 4;
        const float* row = topo + (size_t)i * NN + w4 * 32;
        unsigned b0 = __ballot_sync(0xffffffffu, row[lane]      > -1e8f);
        unsigned b1 = __ballot_sync(0xffffffffu, row[32 + lane] > -1e8f);
        unsigned b2 = __ballot_sync(0xffffffffu, row[64 + lane] > -1e8f);
        unsigned b3 = __ballot_sync(0xffffffffu, row[96 + lane] > -1e8f);
        if (lane < 4) {
            unsigned bb = (lane == 0) ? b0 : (lane == 1) ? b1 : (lane == 2) ? b2 : b3;
            g_maskT[(w4 + lane) * NN + i] = bb;
        }
        return;
    }

    // ---------------- GEMM part ------------------------------------------
    int lane = tid & 31, wid = tid >> 5;
    int g = lane >> 2, t = lane & 3;
    int bm = bid & 31, bn = bid >> 5;
    int wm = (wid & 1) * 64, wn = (wid >> 1) * 32;

    float acc[4][4][4];
    #pragma unroll
    for (int mf = 0; mf < 4; mf++)
        #pragma unroll
        for (int nf = 0; nf < 4; nf++)
            acc[mf][nf][0] = acc[mf][nf][1] = acc[mf][nf][2] = acc[mf][nf][3] = 0.f;

    for (int kc = 0; kc < 4; kc++) {
        __syncthreads();
        #pragma unroll
        for (int it = 0; it < 4; it++) {
            int idx = tid + it * 256;           // 1024: 128 rows x 8 float4
            int r = idx >> 3, kq = idx & 7;
            float4 v = *(const float4*)(x + (size_t)(bm * 128 + r) * FIN + kc * 32 + kq * 4);
            sA[r][kq * 4 + 0] = rndtf32(v.x);
            sA[r][kq * 4 + 1] = rndtf32(v.y);
            sA[r][kq * 4 + 2] = rndtf32(v.z);
            sA[r][kq * 4 + 3] = rndtf32(v.w);
            int c = bn * 128 + r;               // W row (uniform proj/skw per block)
            int kb = kc * 32 + kq * 4;
            if (bn < 4) {                       // proj: W[c][k] = proj[c>>6][k][c&63]
                const float* pp = proj + (c >> 6) * (FIN * FOUT) + (c & 63);
                #pragma unroll
                for (int e = 0; e < 4; e++)
                    sB[r][kq * 4 + e] = rndtf32(pp[(kb + e) * FOUT]);
            } else {                            // skw: contiguous
                float4 w = *(const float4*)(skw + (size_t)(c - 512) * FIN + kb);
                sB[r][kq * 4 + 0] = rndtf32(w.x);
                sB[r][kq * 4 + 1] = rndtf32(w.y);
                sB[r][kq * 4 + 2] = rndtf32(w.z);
                sB[r][kq * 4 + 3] = rndtf32(w.w);
            }
        }
        __syncthreads();
        #pragma unroll
        for (int ks = 0; ks < 4; ks++) {
            int kk = ks * 8;
            uint32_t a[4][4], b[4][2];
            #pragma unroll
            for (int mf = 0; mf < 4; mf++) {
                a[mf][0] = __float_as_uint(sA[wm + mf * 16 + g][kk + t]);
                a[mf][1] = __float_as_uint(sA[wm + mf * 16 + 8 + g][kk + t]);
                a[mf][2] = __float_as_uint(sA[wm + mf * 16 + g][kk + 4 + t]);
                a[mf][3] = __float_as_uint(sA[wm + mf * 16 + 8 + g][kk + 4 + t]);
            }
            #pragma unroll
            for (int nf = 0; nf < 4; nf++) {
                b[nf][0] = __float_as_uint(sB[wn + nf * 8 + g][kk + t]);
                b[nf][1] = __float_as_uint(sB[wn + nf * 8 + g][kk + 4 + t]);
            }
            #pragma unroll
            for (int mf = 0; mf < 4; mf++)
                #pragma unroll
                for (int nf = 0; nf < 4; nf++)
                    asm("mma.sync.aligned.m16n8k8.row.col.f32.tf32.tf32.f32 "
                        "{%0,%1,%2,%3}, {%4,%5,%6,%7}, {%8,%9}, {%0,%1,%2,%3};"
                        : "+f"(acc[mf][nf][0]), "+f"(acc[mf][nf][1]),
                          "+f"(acc[mf][nf][2]), "+f"(acc[mf][nf][3])
                        : "r"(a[mf][0]), "r"(a[mf][1]), "r"(a[mf][2]), "r"(a[mf][3]),
                          "r"(b[nf][0]), "r"(b[nf][1]));
        }
    }

    #pragma unroll
    for (int mf = 0; mf < 4; mf++)
        #pragma unroll
        for (int nf = 0; nf < 4; nf++) {
            int m = bm * 128 + wm + mf * 16;
            int col = bn * 128 + wn + nf * 8 + 2 * t;
            float2 v0; v0.x = acc[mf][nf][0]; v0.y = acc[mf][nf][1];
            float2 v1; v1.x = acc[mf][nf][2]; v1.y = acc[mf][nf][3];
            *(float2*)(g_hs + (size_t)(m + g) * CT + col)     = v0;
            *(float2*)(g_hs + (size_t)(m + 8 + g) * CT + col) = v1;
        }
}

// fragment-gather permutation within each 16-j group:
__device__ __forceinline__ int fragperm(int k) {
    return (k < 8) ? ((k >> 1) * 4 + (k & 1))
                   : (((k - 8) >> 1) * 4 + 2 + (k & 1));
}

// ------- fused transpose (h -> f16 frag-permuted hH) + s_src/s_dst --------
// grid (32 quad-tiles, 8 heads), block 256 = (32 j, 8 o-groups); 4 j-tiles/block.
__global__ void k_transp(const float* __restrict__ wsrc, const float* __restrict__ wdst) {
    __shared__ float s[32][68];
    __shared__ float sw[64], swd[64];
    __shared__ float red[2][8][32];
    int h = blockIdx.y;
    int tid = threadIdx.x;
    int x = tid & 31, y = tid >> 5;

    if (tid < 64)       sw[tid]        = wsrc[h * 64 + tid];
    else if (tid < 128) swd[tid - 64]  = wdst[h * 64 + tid - 64];

    for (int q4 = 0; q4 < 4; q4++) {
        int jt = blockIdx.x * 4 + q4;
        __syncthreads();                       // guards s/red reuse + weight visibility
        #pragma unroll
        for (int it = 0; it < 2; it++) {
            int fi = tid + it * 256;           // 512: 32 j-rows x 16 float4
            int j = fi >> 4, q = fi & 15;
            float4 v = *(const float4*)(g_hs + (size_t)(jt * 32 + j) * CT + h * 64 + q * 4);
            *(float4*)(&s[j][q * 4]) = v;
        }
        __syncthreads();

        int jp = jt * 32 + (x >> 4) * 16 + fragperm(x & 15);
        #pragma unroll
        for (int r = 0; r < 8; r++) {
            int o = y + r * 8;
            g_hH[(h * 64 + o) * NN + jp] = __float2half_rn(s[x][o]);
        }

        float pss = 0.f, psd = 0.f;
        #pragma unroll
        for (int c = 0; c < 8; c++) {
            float v = s[x][y * 8 + c];
            pss += v * sw[y * 8 + c];
            psd += v * swd[y * 8 + c];
        }
        red[0][y][x] = pss;
        red[1][y][x] = psd;
        __syncthreads();
        if (tid < 32) {
            float a = 0.f, b = 0.f;
            #pragma unroll
            for (int yy = 0; yy < 8; yy++) { a += red[0][yy][tid]; b += red[1][yy][tid]; }
            g_ssrc[h * NN + jt * 32 + tid] = a * LOG2E;
            g_sdst[h * NN + jt * 32 + tid] = b * LOG2E;
        }
    }
}

// ---------------- B tile loader: g_hH[64 o][128 j'] -> smem (stride 144) --
__device__ __forceinline__ void load_btile(const __half* __restrict__ hH, int jt,
                                           uint32_t bufb, int tid) {
    #pragma unroll
    for (int c = 0; c < 4; c++) {
        int idx = tid + c * 256;             // 1024 chunks: 64 rows x 16 x 16B
        int o = idx >> 4, ck = idx & 15;
        uint32_t dst = bufb + (uint32_t)(o * (BS_H * 2) + ck * 16);
        const __half* src = hH + o * NN + jt * 128 + ck * 8;
        asm volatile("cp.async.cg.shared.global [%0], [%1], 16;"
                     :: "r"(dst), "l"(src) : "memory");
    }
}

__device__ __forceinline__ uint32_t pack_h2(float lo, float hi) {
    uint32_t u;
    asm("cvt.rn.f16x2.f32 %0, %1, %2;" : "=r"(u) : "f"(hi), "f"(lo));
    return u;
}

// masked leaky + paired f16x2 exp2 (inputs pre-scaled by log2e)
__device__ __forceinline__ uint32_t pgen2(float ssrc, float2 sd, unsigned m, int sh) {
    float v0 = ssrc + sd.x;
    float v1 = ssrc + sd.y;
    v0 = fmaxf(v0, SLOPE * v0);
    v1 = fmaxf(v1, SLOPE * v1);
    v0 = ((m >> sh) & 1u) ? v0 : -1e5f;
    v1 = ((m >> (sh + 1)) & 1u) ? v1 : -1e5f;
    uint32_t pk = pack_h2(v0, v1);
    uint32_t e;
    asm("ex2.approx.f16x2 %0, %1;" : "=r"(e) : "r"(pk));
    return e;
}

// ---------------- main attention: P-gen + P@h via mma.sync f16 ------------
// grid (32 i-tiles, 8 heads, 2 j-halves), block 256 = 8 warps; warp owns 16 rows.
__global__ void __launch_bounds__(256, 3) k_attn() {
    __shared__ __half   sB[2][64 * BS_H];   // 2 x 18432 B
    __shared__ float    s_sdst[2][128];
    __shared__ unsigned smask[2][128 * 4];  // [row r][word q]

    int tid = threadIdx.x, lane = tid & 31, wid = tid >> 5;
    int g = lane >> 2, t = lane & 3;
    int head = blockIdx.y, ibase = blockIdx.x * 128;
    int jh = blockIdx.z, jt0 = jh * 16;
    int r1 = wid * 16 + g, r2 = r1 + 8;
    int srow = tid & 127, sq = tid >> 7;

    float ssr1 = g_ssrc[head * NN + ibase + r1];
    float ssr2 = g_ssrc[head * NN + ibase + r2];
    const __half* hH = g_hH + (size_t)head * (FOUT * NN);
    uint32_t sb0 = smem_u32(sB);
    const uint32_t ONES = 0x3C003C00u;      // (1.0h, 1.0h)

    float acc[8][4], accR[4];
    #pragma unroll
    for (int nt = 0; nt < 8; nt++)
        acc[nt][0] = acc[nt][1] = acc[nt][2] = acc[nt][3] = 0.f;
    accR[0] = accR[1] = accR[2] = accR[3] = 0.f;

    // prologue: stage jt0 (regs -> smem buf 0), start B(jt0)
    float    sd_r = (tid < 128) ? g_sdst[head * NN + jt0 * 128 + tid] : 0.f;
    unsigned mA = g_maskT[(jt0 * 4 + sq) * NN + ibase + srow];
    unsigned mB = g_maskT[(jt0 * 4 + 2 + sq) * NN + ibase + srow];
    if (tid < 128) s_sdst[0][tid] = sd_r;
    smask[0][srow * 4 + sq]     = mA;
    smask[0][srow * 4 + 2 + sq] = mB;
    load_btile(hH, jt0, sb0, tid);
    asm volatile("cp.async.commit_group;" ::: "memory");

    for (int jt = jt0; jt < jt0 + 16; jt++) {
        if (jt < jt0 + 15) {
            if (tid < 128) sd_r = g_sdst[head * NN + (jt + 1) * 128 + tid];
            mA = g_maskT[((jt + 1) * 4 + sq) * NN + ibase + srow];
            mB = g_maskT[((jt + 1) * 4 + 2 + sq) * NN + ibase + srow];
        }

        asm volatile("cp.async.wait_group 0;" ::: "memory");
        __syncthreads();

        if (jt < jt0 + 15) {
            load_btile(hH, jt + 1, sb0 + (uint32_t)(((jt + 1) & 1) * (64 * BS_H * 2)), tid);
            asm volatile("cp.async.commit_group;" ::: "memory");
        }

        const __half*   buf = sB[jt & 1];
        const float*    sds = s_sdst[jt & 1];
        const unsigned* msk = smask[jt & 1];

        #pragma unroll
        for (int c = 0; c < 8; c++) {
            int kb = c * 16;
            float2 sdA = *(const float2*)(sds + kb + 2 * t);
            float2 sdB = *(const float2*)(sds + kb + 2 * t + 8);
            unsigned m1 = msk[r1 * 4 + (c >> 1)];
            unsigned m2 = msk[r2 * 4 + (c >> 1)];
            int sb = (c & 1) * 16 + 2 * t;

            uint32_t a0 = pgen2(ssr1, sdA, m1, sb);
            uint32_t a1 = pgen2(ssr2, sdA, m2, sb);
            uint32_t a2 = pgen2(ssr1, sdB, m1, sb + 8);
            uint32_t a3 = pgen2(ssr2, sdB, m2, sb + 8);

            const __half* bp = buf + g * BS_H + kb + 4 * t;
            #pragma unroll
            for (int nt = 0; nt < 8; nt++) {
                uint2 bv = *(const uint2*)(bp + nt * (8 * BS_H));
                asm("mma.sync.aligned.m16n8k16.row.col.f32.f16.f16.f32 "
                    "{%0,%1,%2,%3}, {%4,%5,%6,%7}, {%8,%9}, {%0,%1,%2,%3};"
                    : "+f"(acc[nt][0]), "+f"(acc[nt][1]),
                      "+f"(acc[nt][2]), "+f"(acc[nt][3])
                    : "r"(a0), "r"(a1), "r"(a2), "r"(a3), "r"(bv.x), "r"(bv.y));
            }
            asm("mma.sync.aligned.m16n8k16.row.col.f32.f16.f16.f32 "
                "{%0,%1,%2,%3}, {%4,%5,%6,%7}, {%8,%9}, {%0,%1,%2,%3};"
                : "+f"(accR[0]), "+f"(accR[1]), "+f"(accR[2]), "+f"(accR[3])
                : "r"(a0), "r"(a1), "r"(a2), "r"(a3), "r"(ONES), "r"(ONES));
        }

        if (jt < jt0 + 15) {
            if (tid < 128) s_sdst[(jt + 1) & 1][tid] = sd_r;
            smask[(jt + 1) & 1][srow * 4 + sq]     = mA;
            smask[(jt + 1) & 1][srow * 4 + 2 + sq] = mB;
        }
    }

    // store unnormalized partials + partial row-sums
    float* o1 = g_attnP[jh] + (size_t)(head * NN + ibase + r1) * FOUT + 2 * t;
    float* o2 = g_attnP[jh] + (size_t)(head * NN + ibase + r2) * FOUT + 2 * t;
    #pragma unroll
    for (int nt = 0; nt < 8; nt++) {
        float2 v1; v1.x = acc[nt][0]; v1.y = acc[nt][1];
        float2 v2; v2.x = acc[nt][2]; v2.y = acc[nt][3];
        *(float2*)(o1 + nt * 8) = v1;
        *(float2*)(o2 + nt * 8) = v2;
    }
    if (t == 0) {
        g_rsP[jh][head * NN + ibase + r1] = accR[0];
        g_rsP[jh][head * NN + ibase + r2] = accR[2];
    }
}

// -------- finalize: combine j-halves, mean over heads (+ skip), LeakyReLU --
__global__ void k_final(float* __restrict__ out) {
    __shared__ float s_inv[32];     // [i-sub][head]
    int ib = blockIdx.x * 4;
    int tid = threadIdx.x;
    if (tid < 32) {
        int ii = tid >> 3, h = tid & 7;
        float r = g_rsP[0][h * NN + ib + ii] + g_rsP[1][h * NN + ib + ii];
        s_inv[tid] = 1.0f / r;
    }
    __syncthreads();
    int ii = tid >> 6, o = tid & 63;
    int i = ib + ii;
    float s = 0.f;
    #pragma unroll
    for (int h = 0; h < NH; h++) {
        float a = g_attnP[0][(size_t)(h * NN + i) * FOUT + o]
                + g_attnP[1][(size_t)(h * NN + i) * FOUT + o];
        s += a * s_inv[ii * 8 + h] + g_hs[(size_t)i * CT + 512 + h * 64 + o];
    }
    s *= 0.125f;
    out[blockIdx.x * 256 + tid] = fmaxf(s, SLOPE * s);
}

// ---------------- launch ---------------------------------------------------
extern "C" void kernel_launch(void* const* d_in, const int* in_sizes, int n_in,
                              void* d_out, int out_size) {
    const float* x    = (const float*)d_in[0];   // [4096,128]
    const float* topo = (const float*)d_in[1];   // [4096,4096]
    const float* proj = (const float*)d_in[2];   // [8,128,64]
    const float* wsrc = (const float*)d_in[3];   // [8,64]
    const float* wdst = (const float*)d_in[4];   // [8,64]
    const float* skw  = (const float*)d_in[5];   // [512,128]
    float* out = (float*)d_out;                  // [4096,64]

    k_prep<<<16640, 256>>>(x, topo, proj, skw);  // gemm (256 blocks) + mask (16384)
    k_transp<<<dim3(32, 8), 256>>>(wsrc, wdst);
    k_attn<<<dim3(32, 8, 2), 256>>>();
    k_final<<<1024, 256>>>(out);
}

// round 16
// speedup vs baseline: 1.3337x; 1.3337x over previous
#include <cuda_runtime.h>
#include <cuda_fp16.h>
#include <cstdint>

#define NN   4096
#define FIN  128
#define FOUT 64
#define NH   8
#define CT   1024
#define SLOPE 0.2f
#define BS_H 144   // halves per B smem row: 128 data + 16 pad (word-stride 72 ≡ 8 mod 32)
#define LOG2E 1.4426950408889634f

// ---------------- scratch (device globals; no allocations) ----------------
__device__ float    g_Wt[CT * FIN];           // packed weights [1024 c][128 k], tf32-rounded
__device__ float    g_hs[NN * CT];            // [n][1024]: 0..511 h per head, 512..1023 skip
__device__ __half   g_hH[NH * FOUT * NN];     // [h][o][j], f16, j 16-groups frag-permuted
__device__ float    g_ssrc[NH * NN];          // pre-scaled by log2(e)
__device__ float    g_sdst[NH * NN];          // pre-scaled by log2(e)
__device__ unsigned g_maskT[(NN / 32) * NN];  // [word w][i] transposed adjacency bitmask
__device__ float    g_attn[NH * NN * FOUT];   // normalized per-head attention output

__device__ __forceinline__ uint32_t smem_u32(const void* p) {
    uint32_t a;
    asm("{ .reg .u64 t; cvta.to.shared.u64 t, %1; cvt.u32.u64 %0, t; }" : "=r"(a) : "l"(p));
    return a;
}

__device__ __forceinline__ float rndtf32(float v) {
    uint32_t u;
    asm("cvt.rna.tf32.f32 %0, %1;" : "=r"(u) : "f"(v));
    return __uint_as_float(u);
}

// ---------------- pack proj + skip_w^T (transposed, tf32-rounded) ---------
__global__ void k_pack_w(const float* __restrict__ proj, const float* __restrict__ skw) {
    int idx = blockIdx.x * 256 + threadIdx.x;   // 0..131071
    int c = idx >> 7, k = idx & 127;
    float v = (c < 512) ? proj[(c >> 6) * (FIN * FOUT) + k * FOUT + (c & 63)]
                        : skw[(c - 512) * FIN + k];
    g_Wt[idx] = rndtf32(v);
}

// ---------------- adjacency bitmask (transposed: [word][i]) ---------------
__global__ void k_mask(const float* __restrict__ topo) {
    int wt = blockIdx.x * 8 + (threadIdx.x >> 5);   // 0..131071
    int lane = threadIdx.x & 31;
    int i = wt >> 5, w4 = (wt & 31) * 4;
    const float* row = topo + (size_t)i * NN + w4 * 32;
    unsigned b0 = __ballot_sync(0xffffffffu, row[lane]      > -1e8f);
    unsigned b1 = __ballot_sync(0xffffffffu, row[32 + lane] > -1e8f);
    unsigned b2 = __ballot_sync(0xffffffffu, row[64 + lane] > -1e8f);
    unsigned b3 = __ballot_sync(0xffffffffu, row[96 + lane] > -1e8f);
    if (lane < 4) {
        unsigned bb = (lane == 0) ? b0 : (lane == 1) ? b1 : (lane == 2) ? b2 : b3;
        g_maskT[(w4 + lane) * NN + i] = bb;
    }
}

// ---------------- GEMM (tf32 tensor cores): g_hs = x @ Wt^T ---------------
__global__ void __launch_bounds__(256) k_gemm(const float* __restrict__ x) {
    __shared__ float sA[128][36];
    __shared__ float sB[128][36];
    int tid = threadIdx.x, lane = tid & 31, wid = tid >> 5;
    int g = lane >> 2, t = lane & 3;
    int bm = blockIdx.x, bn = blockIdx.y;
    int wm = (wid & 1) * 64, wn = (wid >> 1) * 32;

    float acc[4][4][4];
    #pragma unroll
    for (int mf = 0; mf < 4; mf++)
        #pragma unroll
        for (int nf = 0; nf < 4; nf++)
            acc[mf][nf][0] = acc[mf][nf][1] = acc[mf][nf][2] = acc[mf][nf][3] = 0.f;

    for (int kc = 0; kc < 4; kc++) {
        __syncthreads();
        #pragma unroll
        for (int it = 0; it < 4; it++) {
            int idx = tid + it * 256;
            int r = idx >> 3, kq = idx & 7;
            float4 v = *(const float4*)(x + (size_t)(bm * 128 + r) * FIN + kc * 32 + kq * 4);
            sA[r][kq * 4 + 0] = rndtf32(v.x);
            sA[r][kq * 4 + 1] = rndtf32(v.y);
            sA[r][kq * 4 + 2] = rndtf32(v.z);
            sA[r][kq * 4 + 3] = rndtf32(v.w);
            float4 w = *(const float4*)(g_Wt + (size_t)(bn * 128 + r) * FIN + kc * 32 + kq * 4);
            *(float4*)(&sB[r][kq * 4]) = w;
        }
        __syncthreads();
        #pragma unroll
        for (int ks = 0; ks < 4; ks++) {
            int kk = ks * 8;
            uint32_t a[4][4], b[4][2];
            #pragma unroll
            for (int mf = 0; mf < 4; mf++) {
                a[mf][0] = __float_as_uint(sA[wm + mf * 16 + g][kk + t]);
                a[mf][1] = __float_as_uint(sA[wm + mf * 16 + 8 + g][kk + t]);
                a[mf][2] = __float_as_uint(sA[wm + mf * 16 + g][kk + 4 + t]);
                a[mf][3] = __float_as_uint(sA[wm + mf * 16 + 8 + g][kk + 4 + t]);
            }
            #pragma unroll
            for (int nf = 0; nf < 4; nf++) {
                b[nf][0] = __float_as_uint(sB[wn + nf * 8 + g][kk + t]);
                b[nf][1] = __float_as_uint(sB[wn + nf * 8 + g][kk + 4 + t]);
            }
            #pragma unroll
            for (int mf = 0; mf < 4; mf++)
                #pragma unroll
                for (int nf = 0; nf < 4; nf++)
                    asm volatile(
                        "mma.sync.aligned.m16n8k8.row.col.f32.tf32.tf32.f32 "
                        "{%0,%1,%2,%3}, {%4,%5,%6,%7}, {%8,%9}, {%0,%1,%2,%3};"
                        : "+f"(acc[mf][nf][0]), "+f"(acc[mf][nf][1]),
                          "+f"(acc[mf][nf][2]), "+f"(acc[mf][nf][3])
                        : "r"(a[mf][0]), "r"(a[mf][1]), "r"(a[mf][2]), "r"(a[mf][3]),
                          "r"(b[nf][0]), "r"(b[nf][1]));
        }
    }

    #pragma unroll
    for (int mf = 0; mf < 4; mf++)
        #pragma unroll
        for (int nf = 0; nf < 4; nf++) {
            int m = bm * 128 + wm + mf * 16;
            int col = bn * 128 + wn + nf * 8 + 2 * t;
            float2 v0; v0.x = acc[mf][nf][0]; v0.y = acc[mf][nf][1];
            float2 v1; v1.x = acc[mf][nf][2]; v1.y = acc[mf][nf][3];
            *(float2*)(g_hs + (size_t)(m + g) * CT + col)     = v0;
            *(float2*)(g_hs + (size_t)(m + 8 + g) * CT + col) = v1;
        }
}

// fragment-gather permutation within each 16-j group:
__device__ __forceinline__ int fragperm(int k) {
    return (k < 8) ? ((k >> 1) * 4 + (k & 1))
                   : (((k - 8) >> 1) * 4 + 2 + (k & 1));
}

// ------- fused transpose (h -> f16 frag-permuted hH) + s_src/s_dst --------
// grid (32 quad-tiles, 8 heads), block 256 = (32 j, 8 o-groups); 4 j-tiles/block.
__global__ void k_transp(const float* __restrict__ wsrc, const float* __restrict__ wdst) {
    __shared__ float s[32][68];
    __shared__ float sw[64], swd[64];
    __shared__ float red[2][8][32];
    int h = blockIdx.y;
    int tid = threadIdx.x;
    int x = tid & 31, y = tid >> 5;

    if (tid < 64)       sw[tid]        = wsrc[h * 64 + tid];
    else if (tid < 128) swd[tid - 64]  = wdst[h * 64 + tid - 64];

    for (int q4 = 0; q4 < 4; q4++) {
        int jt = blockIdx.x * 4 + q4;
        __syncthreads();                       // guards s/red reuse + weight visibility
        #pragma unroll
        for (int it = 0; it < 2; it++) {
            int fi = tid + it * 256;           // 512: 32 j-rows x 16 float4
            int j = fi >> 4, q = fi & 15;
            float4 v = *(const float4*)(g_hs + (size_t)(jt * 32 + j) * CT + h * 64 + q * 4);
            *(float4*)(&s[j][q * 4]) = v;
        }
        __syncthreads();

        int jp = jt * 32 + (x >> 4) * 16 + fragperm(x & 15);
        #pragma unroll
        for (int r = 0; r < 8; r++) {
            int o = y + r * 8;
            g_hH[(h * 64 + o) * NN + jp] = __float2half_rn(s[x][o]);
        }

        float pss = 0.f, psd = 0.f;
        #pragma unroll
        for (int c = 0; c < 8; c++) {
            float v = s[x][y * 8 + c];
            pss += v * sw[y * 8 + c];
            psd += v * swd[y * 8 + c];
        }
        red[0][y][x] = pss;
        red[1][y][x] = psd;
        __syncthreads();
        if (tid < 32) {
            float a = 0.f, b = 0.f;
            #pragma unroll
            for (int yy = 0; yy < 8; yy++) { a += red[0][yy][tid]; b += red[1][yy][tid]; }
            g_ssrc[h * NN + jt * 32 + tid] = a * LOG2E;
            g_sdst[h * NN + jt * 32 + tid] = b * LOG2E;
        }
    }
}

// ---------------- B tile loader: g_hH[64 o][128 j'] -> smem (stride 144) --
__device__ __forceinline__ void load_btile(const __half* __restrict__ hH, int jt,
                                           uint32_t bufb, int tid) {
    #pragma unroll
    for (int c = 0; c < 4; c++) {
        int idx = tid + c * 256;             // 1024 chunks: 64 rows x 16 x 16B
        int o = idx >> 4, ck = idx & 15;
        uint32_t dst = bufb + (uint32_t)(o * (BS_H * 2) + ck * 16);
        const __half* src = hH + o * NN + jt * 128 + ck * 8;
        asm volatile("cp.async.cg.shared.global [%0], [%1], 16;"
                     :: "r"(dst), "l"(src) : "memory");
    }
}

__device__ __forceinline__ uint32_t pack_h2(float lo, float hi) {
    uint32_t u;
    asm("cvt.rn.f16x2.f32 %0, %1, %2;" : "=r"(u) : "f"(hi), "f"(lo));
    return u;
}

// masked leaky + paired f16x2 exp2 (inputs pre-scaled by log2e)
__device__ __forceinline__ uint32_t pgen2(float ssrc, float2 sd, unsigned m, int sh) {
    float v0 = ssrc + sd.x;
    float v1 = ssrc + sd.y;
    v0 = fmaxf(v0, SLOPE * v0);
    v1 = fmaxf(v1, SLOPE * v1);
    v0 = ((m >> sh) & 1u) ? v0 : -1e5f;
    v1 = ((m >> (sh + 1)) & 1u) ? v1 : -1e5f;
    uint32_t pk = pack_h2(v0, v1);
    uint32_t e;
    asm("ex2.approx.f16x2 %0, %1;" : "=r"(e) : "r"(pk));
    return e;
}

// ---------------- main attention: P-gen + P@h via mma.sync f16 ------------
// grid (32 i-tiles, 8 heads), block 256 = 8 warps; warp owns 16 i-rows.
// Row-sums accumulated by an extra mma against an all-ones B fragment.
__global__ void __launch_bounds__(256, 3) k_attn() {
    __shared__ __half   sB[2][64 * BS_H];   // 2 x 18432 B
    __shared__ float    s_sdst[2][128];
    __shared__ unsigned smask[2][128 * 4];  // [row r][word q]

    int tid = threadIdx.x, lane = tid & 31, wid = tid >> 5;
    int g = lane >> 2, t = lane & 3;
    int head = blockIdx.y, ibase = blockIdx.x * 128;
    int r1 = wid * 16 + g, r2 = r1 + 8;
    int srow = tid & 127, sq = tid >> 7;

    float ssr1 = g_ssrc[head * NN + ibase + r1];
    float ssr2 = g_ssrc[head * NN + ibase + r2];
    const __half* hH = g_hH + (size_t)head * (FOUT * NN);
    uint32_t sb0 = smem_u32(sB);
    const uint32_t ONES = 0x3C003C00u;      // (1.0h, 1.0h)

    float acc[8][4], accR[4];
    #pragma unroll
    for (int nt = 0; nt < 8; nt++)
        acc[nt][0] = acc[nt][1] = acc[nt][2] = acc[nt][3] = 0.f;
    accR[0] = accR[1] = accR[2] = accR[3] = 0.f;

    // prologue: stage jt=0 (regs -> smem buf 0), start B(0)
    float    sd_r = (tid < 128) ? g_sdst[head * NN + tid] : 0.f;
    unsigned mA = g_maskT[sq * NN + ibase + srow];
    unsigned mB = g_maskT[(2 + sq) * NN + ibase + srow];
    if (tid < 128) s_sdst[0][tid] = sd_r;
    smask[0][srow * 4 + sq]     = mA;
    smask[0][srow * 4 + 2 + sq] = mB;
    load_btile(hH, 0, sb0, tid);
    asm volatile("cp.async.commit_group;" ::: "memory");

    for (int jt = 0; jt < 32; jt++) {
        // early gmem prefetch for jt+1 (latency hidden under compute below)
        if (jt < 31) {
            if (tid < 128) sd_r = g_sdst[head * NN + (jt + 1) * 128 + tid];
            mA = g_maskT[((jt + 1) * 4 + sq) * NN + ibase + srow];
            mB = g_maskT[((jt + 1) * 4 + 2 + sq) * NN + ibase + srow];
        }

        asm volatile("cp.async.wait_group 0;" ::: "memory");
        __syncthreads();

        if (jt < 31) {
            load_btile(hH, jt + 1, sb0 + (uint32_t)(((jt + 1) & 1) * (64 * BS_H * 2)), tid);
            asm volatile("cp.async.commit_group;" ::: "memory");
        }

        const __half*   buf = sB[jt & 1];
        const float*    sds = s_sdst[jt & 1];
        const unsigned* msk = smask[jt & 1];

        #pragma unroll
        for (int c = 0; c < 8; c++) {
            int kb = c * 16;
            float2 sdA = *(const float2*)(sds + kb + 2 * t);
            float2 sdB = *(const float2*)(sds + kb + 2 * t + 8);
            unsigned m1 = msk[r1 * 4 + (c >> 1)];
            unsigned m2 = msk[r2 * 4 + (c >> 1)];
            int sb = (c & 1) * 16 + 2 * t;

            uint32_t a0 = pgen2(ssr1, sdA, m1, sb);
            uint32_t a1 = pgen2(ssr2, sdA, m2, sb);
            uint32_t a2 = pgen2(ssr1, sdB, m1, sb + 8);
            uint32_t a3 = pgen2(ssr2, sdB, m2, sb + 8);

            const __half* bp = buf + g * BS_H + kb + 4 * t;
            #pragma unroll
            for (int nt = 0; nt < 8; nt++) {
                uint2 bv = *(const uint2*)(bp + nt * (8 * BS_H));
                asm volatile(
                    "mma.sync.aligned.m16n8k16.row.col.f32.f16.f16.f32 "
                    "{%0,%1,%2,%3}, {%4,%5,%6,%7}, {%8,%9}, {%0,%1,%2,%3};"
                    : "+f"(acc[nt][0]), "+f"(acc[nt][1]),
                      "+f"(acc[nt][2]), "+f"(acc[nt][3])
                    : "r"(a0), "r"(a1), "r"(a2), "r"(a3), "r"(bv.x), "r"(bv.y));
            }
            asm volatile(
                "mma.sync.aligned.m16n8k16.row.col.f32.f16.f16.f32 "
                "{%0,%1,%2,%3}, {%4,%5,%6,%7}, {%8,%9}, {%0,%1,%2,%3};"
                : "+f"(accR[0]), "+f"(accR[1]), "+f"(accR[2]), "+f"(accR[3])
                : "r"(a0), "r"(a1), "r"(a2), "r"(a3), "r"(ONES), "r"(ONES));
        }

        if (jt < 31) {
            if (tid < 128) s_sdst[(jt + 1) & 1][tid] = sd_r;
            smask[(jt + 1) & 1][srow * 4 + sq]     = mA;
            smask[(jt + 1) & 1][srow * 4 + 2 + sq] = mB;
        }
    }

    float inv1 = 1.0f / accR[0], inv2 = 1.0f / accR[2];

    float* o1 = g_attn + (size_t)(head * NN + ibase + r1) * FOUT + 2 * t;
    float* o2 = g_attn + (size_t)(head * NN + ibase + r2) * FOUT + 2 * t;
    #pragma unroll
    for (int nt = 0; nt < 8; nt++) {
        float2 v1; v1.x = acc[nt][0] * inv1; v1.y = acc[nt][1] * inv1;
        float2 v2; v2.x = acc[nt][2] * inv2; v2.y = acc[nt][3] * inv2;
        *(float2*)(o1 + nt * 8) = v1;
        *(float2*)(o2 + nt * 8) = v2;
    }
}

// ---------------- finalize: mean over heads (+ skip), LeakyReLU -----------
__global__ void k_final(float* __restrict__ out) {
    int idx = blockIdx.x * 256 + threadIdx.x;
    int i = idx >> 6, o = idx & 63;
    float s = 0.f;
    #pragma unroll
    for (int h = 0; h < NH; h++)
        s += g_attn[(size_t)(h * NN + i) * FOUT + o] + g_hs[(size_t)i * CT + 512 + h * 64 + o];
    s *= 0.125f;
    out[idx] = fmaxf(s, SLOPE * s);
}

// ---------------- launch ---------------------------------------------------
extern "C" void kernel_launch(void* const* d_in, const int* in_sizes, int n_in,
                              void* d_out, int out_size) {
    const float* x    = (const float*)d_in[0];   // [4096,128]
    const float* topo = (const float*)d_in[1];   // [4096,4096]
    const float* proj = (const float*)d_in[2];   // [8,128,64]
    const float* wsrc = (const float*)d_in[3];   // [8,64]
    const float* wdst = (const float*)d_in[4];   // [8,64]
    const float* skw  = (const float*)d_in[5];   // [512,128]
    float* out = (float*)d_out;                  // [4096,64]

    k_pack_w<<<512, 256>>>(proj, skw);
    k_mask<<<16384, 256>>>(topo);
    k_gemm<<<dim3(32, 8), 256>>>(x);
    k_transp<<<dim3(32, 8), 256>>>(wsrc, wdst);
    k_attn<<<dim3(32, 8), 256>>>();
    k_final<<<1024, 256>>>(out);
}

// round 17
// speedup vs baseline: 1.4933x; 1.1197x over previous
#include <cuda_runtime.h>
#include <cuda_fp16.h>
#include <cstdint>

#define NN   4096
#define FIN  128
#define FOUT 64
#define NH   8
#define CT   1024
#define SLOPE 0.2f
#define BS_H 144   // halves per B smem row: 128 data + 16 pad (word-stride 72 ≡ 8 mod 32)
#define LOG2E 1.4426950408889634f

// ---------------- scratch (device globals; no allocations) ----------------
__device__ float    g_Wt[CT * FIN];           // packed weights [1024 c][128 k], tf32-rounded
__device__ float    g_hs[NN * CT];            // [n][1024]: 0..511 h per head, 512..1023 skip
__device__ __half   g_hH[NH * FOUT * NN];     // [h][o][j], f16, j 16-groups frag-permuted
__device__ float    g_ssrc[NH * NN];          // pre-scaled by log2(e)
__device__ float    g_sdst[NH * NN];          // pre-scaled by log2(e)
__device__ unsigned g_maskT[(NN / 32) * NN];  // [word w][i] transposed adjacency bitmask
__device__ float    g_attn[NH * NN * FOUT];   // normalized per-head attention output

__device__ __forceinline__ uint32_t smem_u32(const void* p) {
    uint32_t a;
    asm("{ .reg .u64 t; cvta.to.shared.u64 t, %1; cvt.u32.u64 %0, t; }" : "=r"(a) : "l"(p));
    return a;
}

__device__ __forceinline__ float rndtf32(float v) {
    uint32_t u;
    asm("cvt.rna.tf32.f32 %0, %1;" : "=r"(u) : "f"(v));
    return __uint_as_float(u);
}

// ---------------- pack proj + skip_w^T (transposed, tf32-rounded) ---------
__global__ void k_pack_w(const float* __restrict__ proj, const float* __restrict__ skw) {
    int idx = blockIdx.x * 256 + threadIdx.x;   // 0..131071
    int c = idx >> 7, k = idx & 127;
    float v = (c < 512) ? proj[(c >> 6) * (FIN * FOUT) + k * FOUT + (c & 63)]
                        : skw[(c - 512) * FIN + k];
    g_Wt[idx] = rndtf32(v);
}

// ---------------- adjacency bitmask (transposed: [word][i]) ---------------
__global__ void k_mask(const float* __restrict__ topo) {
    int wt = blockIdx.x * 8 + (threadIdx.x >> 5);   // 0..131071
    int lane = threadIdx.x & 31;
    int i = wt >> 5, w4 = (wt & 31) * 4;
    const float* row = topo + (size_t)i * NN + w4 * 32;
    unsigned b0 = __ballot_sync(0xffffffffu, row[lane]      > -1e8f);
    unsigned b1 = __ballot_sync(0xffffffffu, row[32 + lane] > -1e8f);
    unsigned b2 = __ballot_sync(0xffffffffu, row[64 + lane] > -1e8f);
    unsigned b3 = __ballot_sync(0xffffffffu, row[96 + lane] > -1e8f);
    if (lane < 4) {
        unsigned bb = (lane == 0) ? b0 : (lane == 1) ? b1 : (lane == 2) ? b2 : b3;
        g_maskT[(w4 + lane) * NN + i] = bb;
    }
}

// ---------------- GEMM (tf32 tensor cores): g_hs = x @ Wt^T ---------------
__global__ void __launch_bounds__(256) k_gemm(const float* __restrict__ x) {
    __shared__ float sA[128][36];
    __shared__ float sB[128][36];
    int tid = threadIdx.x, lane = tid & 31, wid = tid >> 5;
    int g = lane >> 2, t = lane & 3;
    int bm = blockIdx.x, bn = blockIdx.y;
    int wm = (wid & 1) * 64, wn = (wid >> 1) * 32;

    float acc[4][4][4];
    #pragma unroll
    for (int mf = 0; mf < 4; mf++)
        #pragma unroll
        for (int nf = 0; nf < 4; nf++)
            acc[mf][nf][0] = acc[mf][nf][1] = acc[mf][nf][2] = acc[mf][nf][3] = 0.f;

    for (int kc = 0; kc < 4; kc++) {
        __syncthreads();
        #pragma unroll
        for (int it = 0; it < 4; it++) {
            int idx = tid + it * 256;
            int r = idx >> 3, kq = idx & 7;
            float4 v = *(const float4*)(x + (size_t)(bm * 128 + r) * FIN + kc * 32 + kq * 4);
            sA[r][kq * 4 + 0] = rndtf32(v.x);
            sA[r][kq * 4 + 1] = rndtf32(v.y);
            sA[r][kq * 4 + 2] = rndtf32(v.z);
            sA[r][kq * 4 + 3] = rndtf32(v.w);
            float4 w = *(const float4*)(g_Wt + (size_t)(bn * 128 + r) * FIN + kc * 32 + kq * 4);
            *(float4*)(&sB[r][kq * 4]) = w;
        }
        __syncthreads();
        #pragma unroll
        for (int ks = 0; ks < 4; ks++) {
            int kk = ks * 8;
            uint32_t a[4][4], b[4][2];
            #pragma unroll
            for (int mf = 0; mf < 4; mf++) {
                a[mf][0] = __float_as_uint(sA[wm + mf * 16 + g][kk + t]);
                a[mf][1] = __float_as_uint(sA[wm + mf * 16 + 8 + g][kk + t]);
                a[mf][2] = __float_as_uint(sA[wm + mf * 16 + g][kk + 4 + t]);
                a[mf][3] = __float_as_uint(sA[wm + mf * 16 + 8 + g][kk + 4 + t]);
            }
            #pragma unroll
            for (int nf = 0; nf < 4; nf++) {
                b[nf][0] = __float_as_uint(sB[wn + nf * 8 + g][kk + t]);
                b[nf][1] = __float_as_uint(sB[wn + nf * 8 + g][kk + 4 + t]);
            }
            #pragma unroll
            for (int mf = 0; mf < 4; mf++)
                #pragma unroll
                for (int nf = 0; nf < 4; nf++)
                    asm volatile(
                        "mma.sync.aligned.m16n8k8.row.col.f32.tf32.tf32.f32 "
                        "{%0,%1,%2,%3}, {%4,%5,%6,%7}, {%8,%9}, {%0,%1,%2,%3};"
                        : "+f"(acc[mf][nf][0]), "+f"(acc[mf][nf][1]),
                          "+f"(acc[mf][nf][2]), "+f"(acc[mf][nf][3])
                        : "r"(a[mf][0]), "r"(a[mf][1]), "r"(a[mf][2]), "r"(a[mf][3]),
                          "r"(b[nf][0]), "r"(b[nf][1]));
        }
    }

    #pragma unroll
    for (int mf = 0; mf < 4; mf++)
        #pragma unroll
        for (int nf = 0; nf < 4; nf++) {
            int m = bm * 128 + wm + mf * 16;
            int col = bn * 128 + wn + nf * 8 + 2 * t;
            float2 v0; v0.x = acc[mf][nf][0]; v0.y = acc[mf][nf][1];
            float2 v1; v1.x = acc[mf][nf][2]; v1.y = acc[mf][nf][3];
            *(float2*)(g_hs + (size_t)(m + g) * CT + col)     = v0;
            *(float2*)(g_hs + (size_t)(m + 8 + g) * CT + col) = v1;
        }
}

// fragment-gather permutation within each 16-j group:
__device__ __forceinline__ int fragperm(int k) {
    return (k < 8) ? ((k >> 1) * 4 + (k & 1))
                   : (((k - 8) >> 1) * 4 + 2 + (k & 1));
}

// ------- fused transpose (h -> f16 frag-permuted hH) + s_src/s_dst --------
// grid (128 j-tiles, 8 heads), block 256 = (32 j, 8 o-groups)  [R14 geometry]
__global__ void k_transp(const float* __restrict__ wsrc, const float* __restrict__ wdst) {
    __shared__ float s[32][68];
    __shared__ float sw[64], swd[64];
    __shared__ float red[2][8][32];
    int jt = blockIdx.x, h = blockIdx.y;
    int tid = threadIdx.x;
    int x = tid & 31, y = tid >> 5;

    if (tid < 64)       sw[tid]        = wsrc[h * 64 + tid];
    else if (tid < 128) swd[tid - 64]  = wdst[h * 64 + tid - 64];
    #pragma unroll
    for (int it = 0; it < 2; it++) {
        int fi = tid + it * 256;      // 512: 32 j-rows x 16 float4
        int j = fi >> 4, q = fi & 15;
        float4 v = *(const float4*)(g_hs + (size_t)(jt * 32 + j) * CT + h * 64 + q * 4);
        *(float4*)(&s[j][q * 4]) = v;
    }
    __syncthreads();

    int jp = jt * 32 + (x >> 4) * 16 + fragperm(x & 15);
    #pragma unroll
    for (int r = 0; r < 8; r++) {
        int o = y + r * 8;
        g_hH[(h * 64 + o) * NN + jp] = __float2half_rn(s[x][o]);
    }

    float pss = 0.f, psd = 0.f;
    #pragma unroll
    for (int c = 0; c < 8; c++) {
        float v = s[x][y * 8 + c];
        pss += v * sw[y * 8 + c];
        psd += v * swd[y * 8 + c];
    }
    red[0][y][x] = pss;
    red[1][y][x] = psd;
    __syncthreads();
    if (tid < 32) {
        float a = 0.f, b = 0.f;
        #pragma unroll
        for (int yy = 0; yy < 8; yy++) { a += red[0][yy][tid]; b += red[1][yy][tid]; }
        g_ssrc[h * NN + jt * 32 + tid] = a * LOG2E;
        g_sdst[h * NN + jt * 32 + tid] = b * LOG2E;
    }
}

// ---------------- B tile loader: g_hH[64 o][128 j'] -> smem (stride 144) --
__device__ __forceinline__ void load_btile(const __half* __restrict__ hH, int jt,
                                           uint32_t bufb, int tid) {
    #pragma unroll
    for (int c = 0; c < 4; c++) {
        int idx = tid + c * 256;             // 1024 chunks: 64 rows x 16 x 16B
        int o = idx >> 4, ck = idx & 15;
        uint32_t dst = bufb + (uint32_t)(o * (BS_H * 2) + ck * 16);
        const __half* src = hH + o * NN + jt * 128 + ck * 8;
        asm volatile("cp.async.cg.shared.global [%0], [%1], 16;"
                     :: "r"(dst), "l"(src) : "memory");
    }
}

__device__ __forceinline__ uint32_t pack_h2(float lo, float hi) {
    uint32_t u;
    asm("cvt.rn.f16x2.f32 %0, %1, %2;" : "=r"(u) : "f"(hi), "f"(lo));
    return u;
}

// masked leaky + paired f16x2 exp2 (inputs pre-scaled by log2e)
__device__ __forceinline__ uint32_t pgen2(float ssrc, float2 sd, unsigned m, int sh) {
    float v0 = ssrc + sd.x;
    float v1 = ssrc + sd.y;
    v0 = fmaxf(v0, SLOPE * v0);
    v1 = fmaxf(v1, SLOPE * v1);
    v0 = ((m >> sh) & 1u) ? v0 : -1e5f;
    v1 = ((m >> (sh + 1)) & 1u) ? v1 : -1e5f;
    uint32_t pk = pack_h2(v0, v1);
    uint32_t e;
    asm("ex2.approx.f16x2 %0, %1;" : "=r"(e) : "r"(pk));
    return e;
}

// ---------------- main attention: P-gen + P@h via mma.sync f16 ------------
// grid (32 i-tiles, 8 heads), block 256 = 8 warps; warp owns 16 i-rows.
// launch_bounds(256,2): 128-reg budget -> no hot-loop spills (occ 2 CTA/SM).
__global__ void __launch_bounds__(256, 2) k_attn() {
    __shared__ __half   sB[2][64 * BS_H];   // 2 x 18432 B
    __shared__ float    s_sdst[2][128];
    __shared__ unsigned smask[2][128 * 4];  // [row r][word q]

    int tid = threadIdx.x, lane = tid & 31, wid = tid >> 5;
    int g = lane >> 2, t = lane & 3;
    int head = blockIdx.y, ibase = blockIdx.x * 128;
    int r1 = wid * 16 + g, r2 = r1 + 8;
    int srow = tid & 127, sq = tid >> 7;

    float ssr1 = g_ssrc[head * NN + ibase + r1];
    float ssr2 = g_ssrc[head * NN + ibase + r2];
    const __half* hH = g_hH + (size_t)head * (FOUT * NN);
    uint32_t sb0 = smem_u32(sB);
    const uint32_t ONES = 0x3C003C00u;      // (1.0h, 1.0h)

    float acc[8][4], accR[4];
    #pragma unroll
    for (int nt = 0; nt < 8; nt++)
        acc[nt][0] = acc[nt][1] = acc[nt][2] = acc[nt][3] = 0.f;
    accR[0] = accR[1] = accR[2] = accR[3] = 0.f;

    // prologue: stage jt=0 (regs -> smem buf 0), start B(0)
    float    sd_r = (tid < 128) ? g_sdst[head * NN + tid] : 0.f;
    unsigned mA = g_maskT[sq * NN + ibase + srow];
    unsigned mB = g_maskT[(2 + sq) * NN + ibase + srow];
    if (tid < 128) s_sdst[0][tid] = sd_r;
    smask[0][srow * 4 + sq]     = mA;
    smask[0][srow * 4 + 2 + sq] = mB;
    load_btile(hH, 0, sb0, tid);
    asm volatile("cp.async.commit_group;" ::: "memory");

    for (int jt = 0; jt < 32; jt++) {
        // early gmem prefetch for jt+1 (latency hidden under compute below)
        if (jt < 31) {
            if (tid < 128) sd_r = g_sdst[head * NN + (jt + 1) * 128 + tid];
            mA = g_maskT[((jt + 1) * 4 + sq) * NN + ibase + srow];
            mB = g_maskT[((jt + 1) * 4 + 2 + sq) * NN + ibase + srow];
        }

        asm volatile("cp.async.wait_group 0;" ::: "memory");
        __syncthreads();

        if (jt < 31) {
            load_btile(hH, jt + 1, sb0 + (uint32_t)(((jt + 1) & 1) * (64 * BS_H * 2)), tid);
            asm volatile("cp.async.commit_group;" ::: "memory");
        }

        const __half*   buf = sB[jt & 1];
        const float*    sds = s_sdst[jt & 1];
        const unsigned* msk = smask[jt & 1];

        #pragma unroll
        for (int c = 0; c < 8; c++) {
            int kb = c * 16;
            float2 sdA = *(const float2*)(sds + kb + 2 * t);
            float2 sdB = *(const float2*)(sds + kb + 2 * t + 8);
            unsigned m1 = msk[r1 * 4 + (c >> 1)];
            unsigned m2 = msk[r2 * 4 + (c >> 1)];
            int sb = (c & 1) * 16 + 2 * t;

            uint32_t a0 = pgen2(ssr1, sdA, m1, sb);
            uint32_t a1 = pgen2(ssr2, sdA, m2, sb);
            uint32_t a2 = pgen2(ssr1, sdB, m1, sb + 8);
            uint32_t a3 = pgen2(ssr2, sdB, m2, sb + 8);

            const __half* bp = buf + g * BS_H + kb + 4 * t;
            #pragma unroll
            for (int nt = 0; nt < 8; nt++) {
                uint2 bv = *(const uint2*)(bp + nt * (8 * BS_H));
                asm volatile(
                    "mma.sync.aligned.m16n8k16.row.col.f32.f16.f16.f32 "
                    "{%0,%1,%2,%3}, {%4,%5,%6,%7}, {%8,%9}, {%0,%1,%2,%3};"
                    : "+f"(acc[nt][0]), "+f"(acc[nt][1]),
                      "+f"(acc[nt][2]), "+f"(acc[nt][3])
                    : "r"(a0), "r"(a1), "r"(a2), "r"(a3), "r"(bv.x), "r"(bv.y));
            }
            asm volatile(
                "mma.sync.aligned.m16n8k16.row.col.f32.f16.f16.f32 "
                "{%0,%1,%2,%3}, {%4,%5,%6,%7}, {%8,%9}, {%0,%1,%2,%3};"
                : "+f"(accR[0]), "+f"(accR[1]), "+f"(accR[2]), "+f"(accR[3])
                : "r"(a0), "r"(a1), "r"(a2), "r"(a3), "r"(ONES), "r"(ONES));
        }

        if (jt < 31) {
            if (tid < 128) s_sdst[(jt + 1) & 1][tid] = sd_r;
            smask[(jt + 1) & 1][srow * 4 + sq]     = mA;
            smask[(jt + 1) & 1][srow * 4 + 2 + sq] = mB;
        }
    }

    float inv1 = 1.0f / accR[0], inv2 = 1.0f / accR[2];

    float* o1 = g_attn + (size_t)(head * NN + ibase + r1) * FOUT + 2 * t;
    float* o2 = g_attn + (size_t)(head * NN + ibase + r2) * FOUT + 2 * t;
    #pragma unroll
    for (int nt = 0; nt < 8; nt++) {
        float2 v1; v1.x = acc[nt][0] * inv1; v1.y = acc[nt][1] * inv1;
        float2 v2; v2.x = acc[nt][2] * inv2; v2.y = acc[nt][3] * inv2;
        *(float2*)(o1 + nt * 8) = v1;
        *(float2*)(o2 + nt * 8) = v2;
    }
}

// ---------------- finalize: mean over heads (+ skip), LeakyReLU -----------
__global__ void k_final(float* __restrict__ out) {
    int idx = blockIdx.x * 256 + threadIdx.x;
    int i = idx >> 6, o = idx & 63;
    float s = 0.f;
    #pragma unroll
    for (int h = 0; h < NH; h++)
        s += g_attn[(size_t)(h * NN + i) * FOUT + o] + g_hs[(size_t)i * CT + 512 + h * 64 + o];
    s *= 0.125f;
    out[idx] = fmaxf(s, SLOPE * s);
}

// ---------------- launch ---------------------------------------------------
extern "C" void kernel_launch(void* const* d_in, const int* in_sizes, int n_in,
                              void* d_out, int out_size) {
    const float* x    = (const float*)d_in[0];   // [4096,128]
    const float* topo = (const float*)d_in[1];   // [4096,4096]
    const float* proj = (const float*)d_in[2];   // [8,128,64]
    const float* wsrc = (const float*)d_in[3];   // [8,64]
    const float* wdst = (const float*)d_in[4];   // [8,64]
    const float* skw  = (const float*)d_in[5];   // [512,128]
    float* out = (float*)d_out;                  // [4096,64]

    k_pack_w<<<512, 256>>>(proj, skw);
    k_mask<<<16384, 256>>>(topo);
    k_gemm<<<dim3(32, 8), 256>>>(x);
    k_transp<<<dim3(128, 8), 256>>>(wsrc, wdst);
    k_attn<<<dim3(32, 8), 256>>>();
    k_final<<<1024, 256>>>(out);
}